// round 1
// baseline (speedup 1.0000x reference)
#include <cuda_runtime.h>

#define RED_BLOCKS   1184   // 8 * 148 SMs
#define RED_THREADS  256
#define SCL_BLOCKS   2368
#define SCL_THREADS  256

__device__ float g_partials[RED_BLOCKS];
__device__ float g_scale;

__device__ __forceinline__ float warp_reduce_f(float v) {
    #pragma unroll
    for (int o = 16; o > 0; o >>= 1) v += __shfl_xor_sync(0xffffffffu, v, o);
    return v;
}

__global__ void __launch_bounds__(RED_THREADS)
reduce_sq_kernel(const float4* __restrict__ p0, long n0,
                 const float4* __restrict__ p1, long n1,
                 const float4* __restrict__ p2, long n2,
                 const float4* __restrict__ p3, long n3,
                 const float4* __restrict__ p4, long n4,
                 const float*  __restrict__ t0, long m0,
                 const float*  __restrict__ t1, long m1,
                 const float*  __restrict__ t2, long m2,
                 const float*  __restrict__ t3, long m3,
                 const float*  __restrict__ t4, long m4)
{
    float acc = 0.0f;
    const long tid    = (long)blockIdx.x * blockDim.x + threadIdx.x;
    const long stride = (long)gridDim.x * blockDim.x;

    const float4* ps[5] = {p0, p1, p2, p3, p4};
    long          ns[5] = {n0, n1, n2, n3, n4};
    #pragma unroll
    for (int t = 0; t < 5; t++) {
        const float4* __restrict__ p = ps[t];
        const long n = ns[t];
        for (long i = tid; i < n; i += stride) {
            float4 v = p[i];
            acc = fmaf(v.x, v.x, acc);
            acc = fmaf(v.y, v.y, acc);
            acc = fmaf(v.z, v.z, acc);
            acc = fmaf(v.w, v.w, acc);
        }
    }
    // scalar tails (normally empty: all sizes divisible by 4)
    const float* ts[5] = {t0, t1, t2, t3, t4};
    long         ms[5] = {m0, m1, m2, m3, m4};
    #pragma unroll
    for (int t = 0; t < 5; t++) {
        for (long i = tid; i < ms[t]; i += stride) {
            float v = ts[t][i];
            acc = fmaf(v, v, acc);
        }
    }

    acc = warp_reduce_f(acc);
    __shared__ float sm[RED_THREADS / 32];
    if ((threadIdx.x & 31) == 0) sm[threadIdx.x >> 5] = acc;
    __syncthreads();
    if (threadIdx.x < 32) {
        float v = (threadIdx.x < RED_THREADS / 32) ? sm[threadIdx.x] : 0.0f;
        v = warp_reduce_f(v);
        if (threadIdx.x == 0) g_partials[blockIdx.x] = v;
    }
}

__global__ void __launch_bounds__(1024)
finalize_kernel()
{
    double acc = 0.0;
    for (int i = threadIdx.x; i < RED_BLOCKS; i += blockDim.x)
        acc += (double)g_partials[i];
    #pragma unroll
    for (int o = 16; o > 0; o >>= 1) acc += __shfl_xor_sync(0xffffffffu, acc, o);
    __shared__ double sd[32];
    if ((threadIdx.x & 31) == 0) sd[threadIdx.x >> 5] = acc;
    __syncthreads();
    if (threadIdx.x < 32) {
        double v = (threadIdx.x < (int)(blockDim.x >> 5)) ? sd[threadIdx.x] : 0.0;
        #pragma unroll
        for (int o = 16; o > 0; o >>= 1) v += __shfl_xor_sync(0xffffffffu, v, o);
        if (threadIdx.x == 0) {
            float norm = sqrtf((float)v);
            g_scale = (norm > 1.0f) ? (1.0f / (norm + 1e-6f)) : 1.0f;
        }
    }
}

__global__ void __launch_bounds__(SCL_THREADS)
scale_kernel(const float4* __restrict__ p0, long n0, long o0,
             const float4* __restrict__ p1, long n1, long o1,
             const float4* __restrict__ p2, long n2, long o2,
             const float4* __restrict__ p3, long n3, long o3,
             const float4* __restrict__ p4, long n4, long o4,
             float4* __restrict__ out,
             const float* __restrict__ tail_in, long tail_n, long tail_off,
             float* __restrict__ out_scalar)
{
    const float s = g_scale;
    const long tid    = (long)blockIdx.x * blockDim.x + threadIdx.x;
    const long stride = (long)gridDim.x * blockDim.x;

    const float4* ps[5] = {p0, p1, p2, p3, p4};
    long          ns[5] = {n0, n1, n2, n3, n4};
    long          os[5] = {o0, o1, o2, o3, o4};
    #pragma unroll
    for (int t = 0; t < 5; t++) {
        const float4* __restrict__ p = ps[t];
        float4* __restrict__ q = out + os[t];
        const long n = ns[t];
        for (long i = tid; i < n; i += stride) {
            float4 v = p[i];
            v.x *= s; v.y *= s; v.z *= s; v.w *= s;
            q[i] = v;
        }
    }
    // scalar tail (normally empty)
    for (long i = tid; i < tail_n; i += stride)
        out_scalar[tail_off + i] = tail_in[i] * s;
}

extern "C" void kernel_launch(void* const* d_in, const int* in_sizes, int n_in,
                              void* d_out, int out_size)
{
    const float* g[5];
    long n[5];
    for (int i = 0; i < 5; i++) {
        g[i] = (const float*)d_in[i];
        n[i] = (long)in_sizes[i];
    }
    long n4[5], tail[5], off4[5];
    long cum = 0;
    for (int i = 0; i < 5; i++) {
        n4[i]   = n[i] >> 2;       // float4 count
        tail[i] = n[i] & 3;        // leftover scalars (0 for these shapes)
        off4[i] = cum >> 2;        // float4 offset into concatenated out
        cum += n[i];
    }

    // Pass 1: sum of squares -> per-block partials
    reduce_sq_kernel<<<RED_BLOCKS, RED_THREADS>>>(
        (const float4*)g[0], n4[0],
        (const float4*)g[1], n4[1],
        (const float4*)g[2], n4[2],
        (const float4*)g[3], n4[3],
        (const float4*)g[4], n4[4],
        g[0] + (n4[0] << 2), tail[0],
        g[1] + (n4[1] << 2), tail[1],
        g[2] + (n4[2] << 2), tail[2],
        g[3] + (n4[3] << 2), tail[3],
        g[4] + (n4[4] << 2), tail[4]);

    // Pass 2: final reduce + scale factor
    finalize_kernel<<<1, 1024>>>();

    // Pass 3: apply scale into concatenated output
    scale_kernel<<<SCL_BLOCKS, SCL_THREADS>>>(
        (const float4*)g[0], n4[0], off4[0],
        (const float4*)g[1], n4[1], off4[1],
        (const float4*)g[2], n4[2], off4[2],
        (const float4*)g[3], n4[3], off4[3],
        (const float4*)g[4], n4[4], off4[4],
        (float4*)d_out,
        g[0], 0L, 0L,           // no scalar tail for these shapes
        (float*)d_out);
}

// round 4
// speedup vs baseline: 1.0225x; 1.0225x over previous
#include <cuda_runtime.h>

#define RED_BLOCKS   1184   // 8 * 148 SMs
#define RED_THREADS  256
#define SCL_BLOCKS   2368
#define SCL_THREADS  256

__device__ float         g_partials[RED_BLOCKS];
__device__ float         g_scale;
__device__ unsigned int  g_count = 0;

__device__ __forceinline__ float warp_reduce_f(float v) {
    #pragma unroll
    for (int o = 16; o > 0; o >>= 1) v += __shfl_xor_sync(0xffffffffu, v, o);
    return v;
}
__device__ __forceinline__ double warp_reduce_d(double v) {
    #pragma unroll
    for (int o = 16; o > 0; o >>= 1) v += __shfl_xor_sync(0xffffffffu, v, o);
    return v;
}

__device__ __forceinline__ float sq4(float4 v, float acc) {
    acc = fmaf(v.x, v.x, acc);
    acc = fmaf(v.y, v.y, acc);
    acc = fmaf(v.z, v.z, acc);
    acc = fmaf(v.w, v.w, acc);
    return acc;
}

// Pass 1: sum of squares over all 5 tensors (forward sweep),
// last block finalizes: reduces partials (double, fixed order) -> g_scale.
__global__ void __launch_bounds__(RED_THREADS)
reduce_sq_kernel(const float4* __restrict__ p0, long n0,
                 const float4* __restrict__ p1, long n1,
                 const float4* __restrict__ p2, long n2,
                 const float4* __restrict__ p3, long n3,
                 const float4* __restrict__ p4, long n4)
{
    float acc = 0.0f;
    const long tid    = (long)blockIdx.x * blockDim.x + threadIdx.x;
    const long stride = (long)gridDim.x * blockDim.x;

    const float4* ps[5] = {p0, p1, p2, p3, p4};
    long          ns[5] = {n0, n1, n2, n3, n4};

    #pragma unroll
    for (int t = 0; t < 5; t++) {
        const float4* __restrict__ p = ps[t];
        const long n = ns[t];
        long i = tid;
        // main loop: 4 independent loads in flight
        for (; i + 3 * stride < n; i += 4 * stride) {
            float4 v0 = p[i];
            float4 v1 = p[i + stride];
            float4 v2 = p[i + 2 * stride];
            float4 v3 = p[i + 3 * stride];
            acc = sq4(v0, acc);
            acc = sq4(v1, acc);
            acc = sq4(v2, acc);
            acc = sq4(v3, acc);
        }
        for (; i < n; i += stride)
            acc = sq4(p[i], acc);
    }

    // block reduce
    acc = warp_reduce_f(acc);
    __shared__ float sm[RED_THREADS / 32];
    if ((threadIdx.x & 31) == 0) sm[threadIdx.x >> 5] = acc;
    __syncthreads();
    if (threadIdx.x < 32) {
        float v = (threadIdx.x < RED_THREADS / 32) ? sm[threadIdx.x] : 0.0f;
        v = warp_reduce_f(v);
        if (threadIdx.x == 0) g_partials[blockIdx.x] = v;
    }

    // last-block finalize
    __shared__ bool is_last;
    if (threadIdx.x == 0) {
        __threadfence();
        unsigned prev = atomicAdd(&g_count, 1u);
        is_last = (prev == (unsigned)gridDim.x - 1u);
    }
    __syncthreads();
    if (is_last) {
        double d = 0.0;
        for (int i = threadIdx.x; i < RED_BLOCKS; i += RED_THREADS)
            d += (double)g_partials[i];
        d = warp_reduce_d(d);
        __shared__ double sd[RED_THREADS / 32];
        if ((threadIdx.x & 31) == 0) sd[threadIdx.x >> 5] = d;
        __syncthreads();
        if (threadIdx.x < 32) {
            double v = (threadIdx.x < RED_THREADS / 32) ? sd[threadIdx.x] : 0.0;
            v = warp_reduce_d(v);
            if (threadIdx.x == 0) {
                float norm = sqrtf((float)v);
                g_scale = (norm > 1.0f) ? (1.0f / (norm + 1e-6f)) : 1.0f;
                g_count = 0;   // reset for next graph replay
            }
        }
    }
}

// Pass 2: apply scale. Traverses in REVERSE (tensor 4 -> 0, descending
// indices) so the tail of the reduce pass's read stream is still L2-resident.
__global__ void __launch_bounds__(SCL_THREADS)
scale_kernel(const float4* __restrict__ p0, long n0, long o0,
             const float4* __restrict__ p1, long n1, long o1,
             const float4* __restrict__ p2, long n2, long o2,
             const float4* __restrict__ p3, long n3, long o3,
             const float4* __restrict__ p4, long n4, long o4,
             float4* __restrict__ out)
{
    const float s = g_scale;
    const long tid    = (long)blockIdx.x * blockDim.x + threadIdx.x;
    const long stride = (long)gridDim.x * blockDim.x;

    // reverse tensor order: 4,3,2,1,0
    const float4* ps[5] = {p4, p3, p2, p1, p0};
    long          ns[5] = {n4, n3, n2, n1, n0};
    long          os[5] = {o4, o3, o2, o1, o0};

    #pragma unroll
    for (int t = 0; t < 5; t++) {
        const float4* __restrict__ p = ps[t];
        float4* __restrict__ q = out + os[t];
        const long n = ns[t];
        long i = tid;
        // 2 independent load/store streams, descending addresses
        for (; i + stride < n; i += 2 * stride) {
            long j0 = n - 1 - i;
            long j1 = n - 1 - (i + stride);
            float4 v0 = p[j0];
            float4 v1 = p[j1];
            v0.x *= s; v0.y *= s; v0.z *= s; v0.w *= s;
            v1.x *= s; v1.y *= s; v1.z *= s; v1.w *= s;
            q[j0] = v0;
            q[j1] = v1;
        }
        if (i < n) {
            long j = n - 1 - i;
            float4 v = p[j];
            v.x *= s; v.y *= s; v.z *= s; v.w *= s;
            q[j] = v;
        }
    }
}

extern "C" void kernel_launch(void* const* d_in, const int* in_sizes, int n_in,
                              void* d_out, int out_size)
{
    const float* g[5];
    long n[5];
    for (int i = 0; i < 5; i++) {
        g[i] = (const float*)d_in[i];
        n[i] = (long)in_sizes[i];
    }
    long n4[5], off4[5];
    long cum = 0;
    for (int i = 0; i < 5; i++) {
        n4[i]   = n[i] >> 2;   // float4 count (all shapes divisible by 4)
        off4[i] = cum >> 2;
        cum += n[i];
    }

    reduce_sq_kernel<<<RED_BLOCKS, RED_THREADS>>>(
        (const float4*)g[0], n4[0],
        (const float4*)g[1], n4[1],
        (const float4*)g[2], n4[2],
        (const float4*)g[3], n4[3],
        (const float4*)g[4], n4[4]);

    scale_kernel<<<SCL_BLOCKS, SCL_THREADS>>>(
        (const float4*)g[0], n4[0], off4[0],
        (const float4*)g[1], n4[1], off4[1],
        (const float4*)g[2], n4[2], off4[2],
        (const float4*)g[3], n4[3], off4[3],
        (const float4*)g[4], n4[4], off4[4],
        (float4*)d_out);
}